// round 17
// baseline (speedup 1.0000x reference)
#include <cuda_runtime.h>
#include <cuda_fp16.h>
#include <cstdint>
#include <math.h>

// Causal attention, B=4, S=4096, D=64, fp32 in/out.
// out = [ attn_vec (B*S*64) | attn_weights (B*S*S) ]
// Tile 128x64 (BK halved): QK acc 32 regs -> 3 CTAs/SM. fp16 mma + ldmatrix.
// Weight normalization fused via per-(b,qt) counter spin (R11 pattern);
// separate tiny finalize kernel for attn_vec.

constexpr int Bb = 4;
constexpr int Ss = 4096;
constexpr int Dh = 64;
constexpr int BQ = 128;
constexpr int BK = 64;
constexpr int NTQ = Ss / BQ;         // 32
constexpr int NTK = Ss / BK;         // 64

// u32-word offsets in dynamic smem
constexpr int OFFW_Q = 0;            // Qh [128][32w]
constexpr int OFFW_K = 4096;         // Kh [64][32w]
constexpr int OFFW_V = 6144;         // Vt [64][32w] (d-major)
constexpr int OFFW_P = 8192;         // Ph [128][32w]
constexpr int SMEM_WORDS = 12288;    // 49152 B
constexpr int SMEM_BYTES = SMEM_WORDS * 4;
// vacc fp32 staging [128][64] overlays words 0..8192 (Q/K/V dead by then)

__device__ float g_rsum[Bb * Ss];
__device__ float g_vec [Bb * Ss * Dh];
__device__ int   g_cnt [Bb * NTQ];

__device__ __forceinline__ unsigned packh2(float lo, float hi) {
    __half2 h = __floats2half2_rn(lo, hi);
    return *(unsigned*)&h;
}

__device__ __forceinline__ void mma16(float& c0, float& c1, float& c2, float& c3,
                                      unsigned a0, unsigned a1, unsigned a2, unsigned a3,
                                      unsigned b0, unsigned b1) {
    asm("mma.sync.aligned.m16n8k16.row.col.f32.f16.f16.f32 "
        "{%0,%1,%2,%3}, {%4,%5,%6,%7}, {%8,%9}, {%0,%1,%2,%3};"
        : "+f"(c0), "+f"(c1), "+f"(c2), "+f"(c3)
        : "r"(a0), "r"(a1), "r"(a2), "r"(a3), "r"(b0), "r"(b1));
}

__device__ __forceinline__ void ldsm4(unsigned& r0, unsigned& r1,
                                      unsigned& r2, unsigned& r3, unsigned addr) {
    asm volatile("ldmatrix.sync.aligned.m8n8.x4.shared.b16 {%0,%1,%2,%3}, [%4];"
                 : "=r"(r0), "=r"(r1), "=r"(r2), "=r"(r3) : "r"(addr));
}

__global__ __launch_bounds__(256, 3)
void attn_score(const float* __restrict__ Q, const float* __restrict__ K,
                const float* __restrict__ V, float* __restrict__ out_w)
{
    extern __shared__ __align__(16) unsigned smu[];
    __half* smh = (__half*)smu;

    const int b  = blockIdx.y;
    const int x  = blockIdx.x;
    const int qt = x >> 6;           // / NTK
    const int kt = x & (NTK - 1);
    const int q0 = qt * BQ, k0 = kt * BK;
    const int tid = threadIdx.x;

    if (kt > 2 * qt + 1) {
        // strictly-upper tile: pure zero-fill of the weights region, then exit
        float* wg = out_w + ((size_t)(b * Ss + q0)) * Ss + k0;
        const float4 z = make_float4(0.f, 0.f, 0.f, 0.f);
        #pragma unroll
        for (int i = 0; i < 8; i++) {
            const int idx = tid + i * 256;
            const int row = idx >> 4;
            const int c4  = (idx & 15) << 2;
            *(float4*)(wg + (size_t)row * Ss + c4) = z;
        }
        return;
    }

    // ---- stage Q [128][64] (fp16, swizzled, pitch 32 words) ----
    const float* Qg = Q + ((size_t)(b * Ss + q0)) * Dh;
    const float* Kg = K + ((size_t)(b * Ss + k0)) * Dh;
    const float* Vg = V + ((size_t)(b * Ss + k0)) * Dh;
    #pragma unroll
    for (int i = 0; i < 8; i++) {
        const int idx = tid + i * 256;
        const int row = idx >> 4;
        const int c4  = (idx & 15) << 2;
        const int bw  = row * 32 + ((c4 >> 1) ^ ((row & 7) << 2));
        float4 q4 = *(const float4*)(Qg + row * Dh + c4);
        *(uint2*)(smu + OFFW_Q + bw) = make_uint2(packh2(q4.x, q4.y), packh2(q4.z, q4.w));
    }
    // ---- stage K [64][64] ----
    #pragma unroll
    for (int i = 0; i < 4; i++) {
        const int idx = tid + i * 256;
        const int row = idx >> 4;
        const int c4  = (idx & 15) << 2;
        const int bw  = row * 32 + ((c4 >> 1) ^ ((row & 7) << 2));
        float4 k4 = *(const float4*)(Kg + row * Dh + c4);
        *(uint2*)(smu + OFFW_K + bw) = make_uint2(packh2(k4.x, k4.y), packh2(k4.z, k4.w));
    }
    // ---- stage V transposed: Vt[d][k] halves, pitch 32 words, swizzled ----
    #pragma unroll
    for (int i = 0; i < 4; i++) {
        const int idx = tid + i * 256;
        const int k   = idx >> 4;            // 0..63
        const int d4  = (idx & 15) << 2;
        float4 v4 = *(const float4*)(Vg + k * Dh + d4);
        float vv[4] = {v4.x, v4.y, v4.z, v4.w};
        #pragma unroll
        for (int j = 0; j < 4; j++) {
            const int d  = d4 + j;
            const int wv = (k >> 1) ^ ((d & 7) << 2);
            smh[((OFFW_V + d * 32 + wv) << 1) + (k & 1)] = __float2half_rn(vv[j]);
        }
    }
    __syncthreads();   // staging complete

    const int w = tid >> 5, lane = tid & 31;
    const int grp = lane >> 2, tig = lane & 3;

    // ldmatrix lane roles
    const unsigned smb = (unsigned)__cvta_generic_to_shared(smu);
    const int lm = lane >> 3, li = lane & 7;
    const int lmA_r = (lm & 1) << 3;
    const int lmA_k = (lm >> 1) << 2;
    const int lmB_r = (lm >> 1) << 3;
    const int lmB_k = (lm & 1) << 2;

    // ---- QK^T: warp tile 64x16 (wm in {0,1}, wn in {0..3}) ----
    const int wm = w & 1, wn = w >> 1;
    float acc[4][2][4];
    #pragma unroll
    for (int i = 0; i < 4; i++)
        #pragma unroll
        for (int j = 0; j < 2; j++)
            #pragma unroll
            for (int c = 0; c < 4; c++) acc[i][j][c] = 0.0f;

    #pragma unroll
    for (int kk = 0; kk < 4; kk++) {
        unsigned ah[4][4];
        #pragma unroll
        for (int am = 0; am < 4; am++) {
            const int row = wm * 64 + am * 16 + lmA_r + li;
            const unsigned addr = smb +
                ((OFFW_Q + row * 32 + (((kk << 3) + lmA_k) ^ ((row & 7) << 2))) << 2);
            ldsm4(ah[am][0], ah[am][1], ah[am][2], ah[am][3], addr);
        }
        unsigned bh[2][2];
        {
            const int row = wn * 16 + lmB_r + li;
            const unsigned addr = smb +
                ((OFFW_K + row * 32 + (((kk << 3) + lmB_k) ^ ((row & 7) << 2))) << 2);
            ldsm4(bh[0][0], bh[0][1], bh[1][0], bh[1][1], addr);
        }
        #pragma unroll
        for (int am = 0; am < 4; am++)
            #pragma unroll
            for (int an = 0; an < 2; an++) {
                float* c = acc[am][an];
                mma16(c[0], c[1], c[2], c[3],
                      ah[am][0], ah[am][1], ah[am][2], ah[am][3],
                      bh[an][0], bh[an][1]);
            }
    }

    // ---- mask + exp; stage fp16 P (own region); rowsum atomics ----
    #pragma unroll
    for (int am = 0; am < 4; am++) {
        const int rl_loc = wm * 64 + am * 16 + grp;
        const int rowl = q0 + rl_loc;
        const int rowh = rowl + 8;
        float rlo = 0.0f, rhi = 0.0f;
        #pragma unroll
        for (int an = 0; an < 2; an++) {
            const int cl_loc = wn * 16 + an * 8 + 2 * tig;
            const int col = k0 + cl_loc;
            float* c = acc[am][an];
            float e0 = (col     <= rowl) ? __expf(c[0] * 0.125f) : 0.0f;
            float e1 = (col + 1 <= rowl) ? __expf(c[1] * 0.125f) : 0.0f;
            float e2 = (col     <= rowh) ? __expf(c[2] * 0.125f) : 0.0f;
            float e3 = (col + 1 <= rowh) ? __expf(c[3] * 0.125f) : 0.0f;
            rlo += e0 + e1; rhi += e2 + e3;

            const int wcol = (cl_loc >> 1) ^ ((grp & 7) << 2);
            smu[OFFW_P + rl_loc * 32 + wcol]       = packh2(e0, e1);
            smu[OFFW_P + (rl_loc + 8) * 32 + wcol] = packh2(e2, e3);
        }
        rlo += __shfl_xor_sync(0xffffffffu, rlo, 1);
        rlo += __shfl_xor_sync(0xffffffffu, rlo, 2);
        rhi += __shfl_xor_sync(0xffffffffu, rhi, 1);
        rhi += __shfl_xor_sync(0xffffffffu, rhi, 2);
        if (tig == 0) {
            atomicAdd(&g_rsum[b * Ss + rowl], rlo);
            atomicAdd(&g_rsum[b * Ss + rowh], rhi);
        }
    }
    __syncthreads();   // P staged; rowsum atomics issued

    // publish rowsum arrival
    if (tid == 0) {
        __threadfence();
        atomicAdd(&g_cnt[b * NTQ + qt], 1);
    }

    // ---- PV partial: warp tile 32x32 (wm2 in {0..3}, wn2 in {0,1}) ----
    const int wm2 = w >> 1, wn2 = w & 1;
    float vacc[2][4][4];
    #pragma unroll
    for (int i = 0; i < 2; i++)
        #pragma unroll
        for (int j = 0; j < 4; j++)
            #pragma unroll
            for (int c = 0; c < 4; c++) vacc[i][j][c] = 0.0f;

    #pragma unroll
    for (int ks = 0; ks < 4; ks++) {
        unsigned pa[2][4];
        #pragma unroll
        for (int am = 0; am < 2; am++) {
            const int row = wm2 * 32 + am * 16 + lmA_r + li;
            const unsigned addr = smb +
                ((OFFW_P + row * 32 + (((ks << 3) + lmA_k) ^ ((row & 7) << 2))) << 2);
            ldsm4(pa[am][0], pa[am][1], pa[am][2], pa[am][3], addr);
        }
        unsigned vb[4][2];
        #pragma unroll
        for (int g = 0; g < 2; g++) {
            const int row = wn2 * 32 + (g << 4) + lmB_r + li;   // d index
            const unsigned addr = smb +
                ((OFFW_V + row * 32 + (((ks << 3) + lmB_k) ^ ((row & 7) << 2))) << 2);
            ldsm4(vb[2*g][0], vb[2*g][1], vb[2*g+1][0], vb[2*g+1][1], addr);
        }
        #pragma unroll
        for (int am = 0; am < 2; am++)
            #pragma unroll
            for (int an = 0; an < 4; an++) {
                float* c = vacc[am][an];
                mma16(c[0], c[1], c[2], c[3],
                      pa[am][0], pa[am][1], pa[am][2], pa[am][3],
                      vb[an][0], vb[an][1]);
            }
    }

    // ---- wait for the whole row's rowsums, then write normalized weights ----
    if (tid == 0) {
        const int target = 2 * qt + 2;
        while (atomicAdd(&g_cnt[b * NTQ + qt], 0) < target) __nanosleep(200);
        __threadfence();   // acquire
    }
    __syncthreads();

    #pragma unroll
    for (int pass = 0; pass < 16; pass++) {
        const int rloc = pass * 8 + w;
        const float inv = 1.0f / __ldcg(&g_rsum[b * Ss + q0 + rloc]);
        const int swp = (rloc & 7) << 2;
        unsigned pw = smu[OFFW_P + rloc * 32 + (lane ^ swp)];
        float2 f0 = __half22float2(*(__half2*)&pw);
        *(float2*)(out_w + ((size_t)(b * Ss + q0 + rloc)) * Ss + k0 + 2 * lane) =
            make_float2(f0.x * inv, f0.y * inv);
    }

    // ---- stage vacc to smem (overlay Q/K/V region, now dead) ----
    float* vsm = (float*)smu;   // [128][64] fp32, words 0..8192
    #pragma unroll
    for (int am = 0; am < 2; am++) {
        const int rl = wm2 * 32 + am * 16 + grp;
        const int rh = rl + 8;
        #pragma unroll
        for (int an = 0; an < 4; an++) {
            const int d  = wn2 * 32 + an * 8 + 2 * tig;
            const int wl = d ^ (grp << 3);
            float* c = vacc[am][an];
            *(float2*)(vsm + rl * 64 + wl) = make_float2(c[0], c[1]);
            *(float2*)(vsm + rh * 64 + wl) = make_float2(c[2], c[3]);
        }
    }
    __syncthreads();

    // ---- row-coalesced atomic flush of vec partials ----
    #pragma unroll
    for (int pass = 0; pass < 8; pass++) {
        const int rloc = pass * 16 + w * 2 + (lane >> 4);
        const int f    = lane & 15;
        const int swv  = (rloc & 7) << 3;
        float* gv = g_vec + ((size_t)(b * Ss + q0 + rloc)) * Dh;
        #pragma unroll
        for (int j = 0; j < 4; j++) {
            float val = vsm[rloc * 64 + ((f + 16 * j) ^ swv)];
            atomicAdd(gv + f + 16 * j, val);
        }
    }
}

// vec = g_vec / rowsum
__global__ __launch_bounds__(256)
void finalize(float* __restrict__ out_vec)
{
    const int idx = blockIdx.x * 256 + threadIdx.x;
    const int row = idx >> 4;
    const int c4  = (idx & 15) << 2;
    const float inv = 1.0f / g_rsum[row];
    float4 v = *(const float4*)(g_vec + (size_t)row * Dh + c4);
    v.x *= inv; v.y *= inv; v.z *= inv; v.w *= inv;
    *(float4*)(out_vec + (size_t)row * Dh + c4) = v;
}

extern "C" void kernel_launch(void* const* d_in, const int* in_sizes, int n_in,
                              void* d_out, int out_size)
{
    const float* Q = (const float*)d_in[0];
    const float* K = (const float*)d_in[1];
    const float* V = (const float*)d_in[2];

    float* out_vec = (float*)d_out;
    float* out_w   = out_vec + (size_t)Bb * Ss * Dh;

    void* p_rsum = nullptr;
    void* p_vec  = nullptr;
    void* p_cnt  = nullptr;
    cudaGetSymbolAddress(&p_rsum, g_rsum);
    cudaGetSymbolAddress(&p_vec,  g_vec);
    cudaGetSymbolAddress(&p_cnt,  g_cnt);
    cudaMemsetAsync(p_rsum, 0, sizeof(float) * Bb * Ss);
    cudaMemsetAsync(p_vec,  0, sizeof(float) * Bb * Ss * Dh);
    cudaMemsetAsync(p_cnt,  0, sizeof(int) * Bb * NTQ);

    cudaFuncSetAttribute(attn_score, cudaFuncAttributeMaxDynamicSharedMemorySize,
                         SMEM_BYTES);

    dim3 gridA(NTQ * NTK, Bb);                 // (qt,kt); upper tiles zero-fill
    attn_score<<<gridA, 256, SMEM_BYTES>>>(Q, K, V, out_w);

    finalize<<<(Bb * Ss * Dh / 4) / 256, 256>>>(out_vec);
}